// round 17
// baseline (speedup 1.0000x reference)
#include <cuda_runtime.h>
#include <cuda_fp16.h>
#include <math.h>
#include <stdint.h>

#define HIDC 256
#define NHEAD 8
#define CLAMP_V 5.0f

static const int NMAXC = 50000;
static const int EMAXC = 320000;

// ---------------- scratch layout ----------------
#define O_QK   ((size_t)0)                          // N*512 (half)
#define O_V    (O_QK   + (size_t)NMAXC*256)         // N*256 (half)
#define O_CA   (O_V    + (size_t)NMAXC*128)         // E*256 (half)
#define O_AQK  (O_CA   + (size_t)EMAXC*128)         // E*256 (half)
#define O_OE   (O_AQK  + (size_t)EMAXC*128)         // E*256 (half)
#define O_SCB  (O_OE   + (size_t)EMAXC*128)         // E*8  (f32, exp(score))
#define O_SSUM (O_SCB  + (size_t)EMAXC*8)           // N*8  (f32)  [contig w/ AGG]
#define O_AGG  (O_SSUM + (size_t)NMAXC*8)           // N*256 (f32)
#define O_ROWV (O_AGG  + (size_t)NMAXC*256)         // N*256 (f32)
#define O_ON   (O_ROWV + (size_t)NMAXC*256)         // N*256 (half)
#define O_HLN  (O_ON   + (size_t)NMAXC*128)         // N*256 (f32)
#define O_HLNT (O_HLN  + (size_t)NMAXC*256)         // N*256 (half)
#define O_FFN  (O_HLNT + (size_t)NMAXC*128)         // N*512 (half)
#define O_WQKV (O_FFN  + (size_t)NMAXC*256)         // 768*256 (half, [N][K])
#define O_WEWB (O_WQKV + (size_t)768*128)           // 512*256 (half)
#define O_WEO  (O_WEWB + (size_t)512*128)           // 256*256 (half)
#define O_WOH  (O_WEO  + (size_t)256*128)           // 256*256 (half)
#define O_WOE  (O_WOH  + (size_t)256*128)           // 256*256 (half)
#define O_W1   (O_WOE  + (size_t)256*128)           // 512*256 (half)
#define O_W2   (O_W1   + (size_t)512*128)           // 256*512 (half)
#define O_TOTAL (O_W2  + (size_t)256*256)

__device__ float g_scratch[O_TOTAL];

static inline int cdiv(int a, int b) { return (a + b - 1) / b; }

// ---------------- helpers ----------------
__device__ __forceinline__ void mma_f16(float c[4], const uint32_t a[4], const uint32_t b[2]) {
    asm volatile(
        "mma.sync.aligned.m16n8k16.row.col.f32.f16.f16.f32 "
        "{%0,%1,%2,%3}, {%4,%5,%6,%7}, {%8,%9}, {%0,%1,%2,%3};"
        : "+f"(c[0]), "+f"(c[1]), "+f"(c[2]), "+f"(c[3])
        : "r"(a[0]), "r"(a[1]), "r"(a[2]), "r"(a[3]), "r"(b[0]), "r"(b[1]));
}

__device__ __forceinline__ void ldsm4(uint32_t& r0, uint32_t& r1, uint32_t& r2, uint32_t& r3,
                                      uint32_t addr) {
    asm volatile("ldmatrix.sync.aligned.m8n8.x4.shared.b16 {%0,%1,%2,%3}, [%4];"
                 : "=r"(r0), "=r"(r1), "=r"(r2), "=r"(r3) : "r"(addr));
}

__device__ __forceinline__ void cp16(uint32_t saddr, const void* g, bool pred) {
    int sz = pred ? 16 : 0;
    asm volatile("cp.async.cg.shared.global [%0], [%1], 16, %2;\n"
                 :: "r"(saddr), "l"(g), "r"(sz));
}
#define CP_COMMIT() asm volatile("cp.async.commit_group;\n" ::)
#define CP_WAIT(n)  asm volatile("cp.async.wait_group %0;\n" :: "n"(n))

__device__ __forceinline__ void redv4(float* addr, float a, float b, float c, float d) {
    asm volatile("red.global.add.v4.f32 [%0], {%1, %2, %3, %4};"
                 :: "l"(addr), "f"(a), "f"(b), "f"(c), "f"(d) : "memory");
}

// ---------------- aqk: 2 edges per warp, all loads in flight ----------------
__global__ void aqk_kernel(const __half* __restrict__ QK, __half* __restrict__ aqk,
                           const int* __restrict__ dst, const int* __restrict__ src, int E) {
    int w = (blockIdx.x * 256 + threadIdx.x) >> 5;
    int lane = threadIdx.x & 31;
    int e0 = w * 2, e1 = w * 2 + 1;
    if (e0 >= E) return;
    bool has1 = e1 < E;
    int dn0 = dst[e0], sn0 = src[e0];
    int dn1 = has1 ? dst[e1] : dn0;
    int sn1 = has1 ? src[e1] : sn0;
    int4 q0 = ((const int4*)(QK + (size_t)dn0 * 512))[lane];
    int4 k0 = ((const int4*)(QK + (size_t)sn0 * 512 + 256))[lane];
    int4 q1 = ((const int4*)(QK + (size_t)dn1 * 512))[lane];
    int4 k1 = ((const int4*)(QK + (size_t)sn1 * 512 + 256))[lane];
    int4 o0, o1;
    __half2* q0h = (__half2*)&q0; __half2* k0h = (__half2*)&k0; __half2* o0h = (__half2*)&o0;
    __half2* q1h = (__half2*)&q1; __half2* k1h = (__half2*)&k1; __half2* o1h = (__half2*)&o1;
#pragma unroll
    for (int i = 0; i < 4; i++) { o0h[i] = __hadd2(q0h[i], k0h[i]); o1h[i] = __hadd2(q1h[i], k1h[i]); }
    ((int4*)(aqk + (size_t)e0 * 256))[lane] = o0;
    if (has1) ((int4*)(aqk + (size_t)e1 * 256))[lane] = o1;
}

// ---------------- gemm_nt: K=256-resident-A fp16 GEMM ----------------
#define SAR 264
#define NTA_BYTES (128 * SAR * 2)
#define SAH 72
#define NTB_TILEH (128 * SAH)
#define NTB_BYTES (NTB_TILEH * 2)
#define GNT_SMEM (NTA_BYTES + 2 * NTB_BYTES)

// ACT: 0 plain, 1 bias+relu, 2 fused edge message
// SCORE: fused score -> exp -> scb + red.add ssum
template <int ACT, int OUTH, int SCORE, int CVTA, int NT>
__global__ __launch_bounds__(256, 2)
void gemm_nt(const void* __restrict__ Av, const __half* __restrict__ B,
             const float* __restrict__ bias,
             void* __restrict__ Cv, int M,
             const int* __restrict__ dst, const int* __restrict__ src,
             const __half* __restrict__ AQK, const float* __restrict__ Aw,
             float* __restrict__ scb, float* __restrict__ ssum) {
    extern __shared__ __half smh[];
    constexpr int Ncol = NT * 128;
    constexpr int NS = 4 * NT;

    const int tid = threadIdx.x;
    const int warp = tid >> 5;
    const int lane = tid & 31;
    const int g = lane >> 2;
    const int t = lane & 3;
    const int warp_m = warp & 3;
    const int warp_n = warp >> 2;
    const int m0 = blockIdx.x * 128;

    const uint32_t sbase = (uint32_t)__cvta_generic_to_shared(smh);
    const uint32_t bbase = sbase + NTA_BYTES;

    const int srow = tid >> 3;
    const int sseg = tid & 7;

    const int lm_row = lane & 15;
    const int lm_k   = (lane >> 4) << 3;

    if (!CVTA) {
        const __half* A = (const __half*)Av;
#pragma unroll
        for (int i = 0; i < 16; i++) {
            int idx = tid + i * 256;
            int row = idx >> 5, seg = idx & 31;
            cp16(sbase + (row * SAR + seg * 8) * 2,
                 A + (size_t)(m0 + row) * 256 + seg * 8, (m0 + row) < M);
        }
    }
#pragma unroll
    for (int u = 0; u < 4; u++) {
        int r = srow + u * 32;
        cp16(bbase + (r * SAH + sseg * 8) * 2, B + (size_t)r * 256 + sseg * 8, true);
    }
    CP_COMMIT();
    if (CVTA) {
        const float* A32 = (const float*)Av;
#pragma unroll
        for (int i = 0; i < 32; i++) {
            int idx = tid + i * 256;
            int row = idx >> 6, c4 = idx & 63;
            float4 v = make_float4(0.f, 0.f, 0.f, 0.f);
            if (m0 + row < M) v = *(const float4*)&A32[(size_t)(m0 + row) * 256 + c4 * 4];
            __half2 h0 = __float22half2_rn(make_float2(v.x, v.y));
            __half2 h1 = __float22half2_rn(make_float2(v.z, v.w));
            *(__half2*)&smh[row * SAR + c4 * 4] = h0;
            *(__half2*)&smh[row * SAR + c4 * 4 + 2] = h1;
        }
    }

    float acc[2][8][4];
#pragma unroll
    for (int i = 0; i < 2; i++)
#pragma unroll
        for (int j = 0; j < 8; j++)
#pragma unroll
            for (int q = 0; q < 4; q++) acc[i][j][q] = 0.0f;

#pragma unroll
    for (int s = 0; s < NS; s++) {
        if (s + 1 < NS) {
            const int nn0 = ((s + 1) >> 2) * 128;
            const int nc0 = ((s + 1) & 3) * 64;
            const int nb = (s + 1) & 1;
#pragma unroll
            for (int u = 0; u < 4; u++) {
                int r = srow + u * 32;
                cp16(bbase + (nb * NTB_TILEH + r * SAH + sseg * 8) * 2,
                     B + (size_t)(nn0 + r) * 256 + nc0 + sseg * 8, true);
            }
            CP_COMMIT();
            CP_WAIT(1);
        } else {
            CP_WAIT(0);
        }
        __syncthreads();

        const uint32_t bbuf = bbase + (s & 1) * NTB_BYTES;
        const int kk_base = (s & 3) * 64;

#pragma unroll
        for (int ks = 0; ks < 4; ks++) {
            const int kk = kk_base + ks * 16;
            const int kkb = ks * 16;
            uint32_t af[2][4];
#pragma unroll
            for (int i = 0; i < 2; i++) {
                int rm = warp_m * 32 + i * 16;
                ldsm4(af[i][0], af[i][1], af[i][2], af[i][3],
                      sbase + ((rm + lm_row) * SAR + kk + lm_k) * 2);
            }
            uint32_t bf[8][2];
#pragma unroll
            for (int jj = 0; jj < 4; jj++) {
                int nb2 = warp_n * 64 + jj * 16;
                uint32_t r0, r1, r2, r3;
                ldsm4(r0, r1, r2, r3, bbuf + ((nb2 + lm_row) * SAH + kkb + lm_k) * 2);
                bf[2 * jj][0] = r0;     bf[2 * jj][1] = r2;
                bf[2 * jj + 1][0] = r1; bf[2 * jj + 1][1] = r3;
            }
#pragma unroll
            for (int i = 0; i < 2; i++)
#pragma unroll
                for (int j = 0; j < 8; j++)
                    mma_f16(acc[i][j], af[i], bf[j]);
        }

        if ((s & 3) == 3) {
            const int n0 = (s >> 2) * 128;
            if (ACT == 2) {
                __half* C = (__half*)Cv;
                float bebv[8];
                int cqv[8];
#pragma unroll
                for (int j = 0; j < 8; j++) {
                    int cq = (n0 >> 1) + warp_n * 32 + j * 4 + t;
                    cqv[j] = cq;
                    bebv[j] = bias[cq];
                }
#pragma unroll
                for (int i = 0; i < 2; i++) {
#pragma unroll
                    for (int half_ = 0; half_ < 2; half_++) {
                        int r = m0 + warp_m * 32 + i * 16 + half_ * 8 + g;
                        if (r >= M) continue;
                        const __half* arow = AQK + (size_t)r * 256;
#pragma unroll
                        for (int j = 0; j < 8; j++) {
                            float ew = acc[i][j][half_ * 2 + 0];
                            float eb = acc[i][j][half_ * 2 + 1] + bebv[j];
                            float aqk = __half2float(arow[cqv[j]]);
                            float c1 = aqk * ew;
                            float c2 = copysignf(sqrtf(fabsf(c1)), c1);
                            C[(size_t)r * 256 + cqv[j]] = __float2half(fmaxf(c2 + eb, 0.f));
                        }
                    }
                }
            } else if (SCORE) {
                __half* C = (__half*)Cv;
                const int h0 = (n0 + warp_n * 64) >> 5;
                float aw0[8], aw1[8];
#pragma unroll
                for (int j4 = 0; j4 < 4; j4++) {
                    int d = j4 * 8 + 2 * t;
                    aw0[2 * j4]     = __ldg(&Aw[d * 8 + h0]);
                    aw0[2 * j4 + 1] = __ldg(&Aw[(d + 1) * 8 + h0]);
                    aw1[2 * j4]     = __ldg(&Aw[d * 8 + h0 + 1]);
                    aw1[2 * j4 + 1] = __ldg(&Aw[(d + 1) * 8 + h0 + 1]);
                }
                float2 bvj[8];
#pragma unroll
                for (int j = 0; j < 8; j++)
                    bvj[j] = *(const float2*)&bias[n0 + warp_n * 64 + j * 8 + 2 * t];
#pragma unroll
                for (int i = 0; i < 2; i++) {
#pragma unroll
                    for (int half_ = 0; half_ < 2; half_++) {
                        int r = m0 + warp_m * 32 + i * 16 + half_ * 8 + g;
                        float s0 = 0.f, s1 = 0.f;
                        if (r < M) {
#pragma unroll
                            for (int j = 0; j < 8; j++) {
                                float ox = acc[i][j][half_ * 2 + 0] + bvj[j].x;
                                float oy = acc[i][j][half_ * 2 + 1] + bvj[j].y;
                                __half2 h2v = __float22half2_rn(make_float2(ox, oy));
                                ox = __half2float(__low2half(h2v));
                                oy = __half2float(__high2half(h2v));
                                int c = n0 + warp_n * 64 + j * 8 + 2 * t;
                                *(__half2*)&C[(size_t)r * Ncol + c] = h2v;
                                if (j < 4) {
                                    s0 += ox * aw0[2 * j] + oy * aw0[2 * j + 1];
                                } else {
                                    s1 += ox * aw1[2 * (j - 4)] + oy * aw1[2 * (j - 4) + 1];
                                }
                            }
                        }
                        s0 += __shfl_xor_sync(0xffffffffu, s0, 1);
                        s0 += __shfl_xor_sync(0xffffffffu, s0, 2);
                        s1 += __shfl_xor_sync(0xffffffffu, s1, 1);
                        s1 += __shfl_xor_sync(0xffffffffu, s1, 2);
                        if (r < M && t == 0) {
                            float e0 = expf(fminf(fmaxf(s0, -CLAMP_V), CLAMP_V));
                            float e1 = expf(fminf(fmaxf(s1, -CLAMP_V), CLAMP_V));
                            scb[(size_t)r * 8 + h0] = e0;
                            scb[(size_t)r * 8 + h0 + 1] = e1;
                            int dn = dst[r];
                            atomicAdd(&ssum[dn * 8 + h0], e0);
                            atomicAdd(&ssum[dn * 8 + h0 + 1], e1);
                        }
                    }
                }
            } else {
#pragma unroll
                for (int j = 0; j < 8; j++) {
                    int c = n0 + warp_n * 64 + j * 8 + 2 * t;
                    float2 bv = make_float2(0.f, 0.f);
                    if (bias) bv = *(const float2*)&bias[c];
#pragma unroll
                    for (int i = 0; i < 2; i++) {
                        int rbase = m0 + warp_m * 32 + i * 16 + g;
#pragma unroll
                        for (int half_ = 0; half_ < 2; half_++) {
                            int r = rbase + half_ * 8;
                            if (r >= M) continue;
                            float ox = acc[i][j][half_ * 2 + 0] + bv.x;
                            float oy = acc[i][j][half_ * 2 + 1] + bv.y;
                            if (ACT == 1) { ox = fmaxf(ox, 0.f); oy = fmaxf(oy, 0.f); }
                            if (OUTH) {
                                *(__half2*)&((__half*)Cv)[(size_t)r * Ncol + c] =
                                    __float22half2_rn(make_float2(ox, oy));
                            } else {
                                *(float2*)&((float*)Cv)[(size_t)r * Ncol + c] =
                                    make_float2(ox, oy);
                            }
                        }
                    }
                }
            }
#pragma unroll
            for (int i = 0; i < 2; i++)
#pragma unroll
                for (int j = 0; j < 8; j++)
#pragma unroll
                    for (int q = 0; q < 4; q++) acc[i][j][q] = 0.0f;
        }
        __syncthreads();
    }
}

// ---------------- fp16 GEMM + fused residual + LayerNorm ----------------
#define LNA_TILEH (64 * SAH)
#define LNA_TILEB (LNA_TILEH * 2)
#define LNB_TILEH (256 * SAH)
#define LNB_TILEB (LNB_TILEH * 2)
#define GLN_SMEM (2 * LNA_TILEB + 2 * LNB_TILEB)

template <int OUT2, int KVAL>
__global__ __launch_bounds__(256, 2)
void gemm_ln(const __half* __restrict__ A, const __half* __restrict__ B,
             const float* __restrict__ bias, const float* __restrict__ resid,
             const float* __restrict__ lng, const float* __restrict__ lnb,
             float* __restrict__ outF, __half* __restrict__ outH, int M) {
    extern __shared__ __half smh[];
    constexpr int KT = KVAL / 64;

    const int tid = threadIdx.x;
    const int warp = tid >> 5;
    const int lane = tid & 31;
    const int g = lane >> 2;
    const int t = lane & 3;
    const int warp_m = warp & 1;
    const int warp_n = warp >> 1;
    const int m0 = blockIdx.x * 64;

    const uint32_t sbase = (uint32_t)__cvta_generic_to_shared(smh);
    const uint32_t bbase = sbase + 2 * LNA_TILEB;

    const int srow = tid >> 3;
    const int sseg = tid & 7;
    const bool apred[2] = { m0 + srow < M, m0 + srow + 32 < M };
    const __half* Aptr = A + (size_t)(m0 + srow) * KVAL + sseg * 8;
    const __half* Bptr = B + (size_t)srow * KVAL + sseg * 8;

    const int lm_row = lane & 15;
    const int lm_k   = (lane >> 4) << 3;

    float acc[2][8][4];
#pragma unroll
    for (int i = 0; i < 2; i++)
#pragma unroll
        for (int j = 0; j < 8; j++)
#pragma unroll
            for (int q = 0; q < 4; q++) acc[i][j][q] = 0.0f;

#pragma unroll
    for (int u = 0; u < 2; u++) {
        int r = srow + u * 32;
        cp16(sbase + (r * SAH + sseg * 8) * 2, Aptr + (size_t)(u * 32) * KVAL, apred[u]);
    }
#pragma unroll
    for (int u = 0; u < 8; u++) {
        int r = srow + u * 32;
        cp16(bbase + (r * SAH + sseg * 8) * 2, Bptr + (size_t)(u * 32) * KVAL, true);
    }
    CP_COMMIT();

#pragma unroll
    for (int kt = 0; kt < KT; kt++) {
        const int buf = kt & 1;
        if (kt + 1 < KT) {
            const int k0 = (kt + 1) << 6;
            const int nb = buf ^ 1;
#pragma unroll
            for (int u = 0; u < 2; u++) {
                int r = srow + u * 32;
                cp16(sbase + (nb * LNA_TILEH + r * SAH + sseg * 8) * 2,
                     Aptr + (size_t)(u * 32) * KVAL + k0, apred[u]);
            }
#pragma unroll
            for (int u = 0; u < 8; u++) {
                int r = srow + u * 32;
                cp16(bbase + (nb * LNB_TILEH + r * SAH + sseg * 8) * 2,
                     Bptr + (size_t)(u * 32) * KVAL + k0, true);
            }
            CP_COMMIT();
            CP_WAIT(1);
        } else {
            CP_WAIT(0);
        }
        __syncthreads();

        const uint32_t abuf = sbase + buf * LNA_TILEB;
        const uint32_t bbuf = bbase + buf * LNB_TILEB;

#pragma unroll
        for (int ks = 0; ks < 4; ks++) {
            const int kk = ks * 16;
            uint32_t af[2][4];
#pragma unroll
            for (int i = 0; i < 2; i++) {
                int rm = warp_m * 32 + i * 16;
                ldsm4(af[i][0], af[i][1], af[i][2], af[i][3],
                      abuf + ((rm + lm_row) * SAH + kk + lm_k) * 2);
            }
            uint32_t bf[8][2];
#pragma unroll
            for (int jj = 0; jj < 4; jj++) {
                int nb2 = warp_n * 64 + jj * 16;
                uint32_t r0, r1, r2, r3;
                ldsm4(r0, r1, r2, r3, bbuf + ((nb2 + lm_row) * SAH + kk + lm_k) * 2);
                bf[2 * jj][0] = r0;     bf[2 * jj][1] = r2;
                bf[2 * jj + 1][0] = r1; bf[2 * jj + 1][1] = r3;
            }
#pragma unroll
            for (int i = 0; i < 2; i++)
#pragma unroll
                for (int j = 0; j < 8; j++)
                    mma_f16(acc[i][j], af[i], bf[j]);
        }
        __syncthreads();
    }

    float* red = (float*)smh;

#pragma unroll
    for (int i = 0; i < 2; i++) {
#pragma unroll
        for (int half_ = 0; half_ < 2; half_++) {
            const int rl = warp_m * 32 + i * 16 + half_ * 8 + g;
            const int r = m0 + rl;
            float s = 0.f, s2 = 0.f;
            if (r < M) {
#pragma unroll
                for (int j = 0; j < 8; j++) {
                    int c = warp_n * 64 + j * 8 + 2 * t;
                    float2 bv = *(const float2*)&bias[c];
                    float2 rv = *(const float2*)&resid[(size_t)r * HIDC + c];
                    float ox = acc[i][j][half_ * 2 + 0] + bv.x + rv.x;
                    float oy = acc[i][j][half_ * 2 + 1] + bv.y + rv.y;
                    acc[i][j][half_ * 2 + 0] = ox;
                    acc[i][j][half_ * 2 + 1] = oy;
                    s += ox + oy;
                    s2 += ox * ox + oy * oy;
                }
            }
            s  += __shfl_xor_sync(0xffffffffu, s, 1);
            s  += __shfl_xor_sync(0xffffffffu, s, 2);
            s2 += __shfl_xor_sync(0xffffffffu, s2, 1);
            s2 += __shfl_xor_sync(0xffffffffu, s2, 2);
            if (t == 0) {
                red[rl * 8 + warp_n] = s;
                red[rl * 8 + 4 + warp_n] = s2;
            }
        }
    }
    __syncthreads();

#pragma unroll
    for (int i = 0; i < 2; i++) {
#pragma unroll
        for (int half_ = 0; half_ < 2; half_++) {
            const int rl = warp_m * 32 + i * 16 + half_ * 8 + g;
            const int r = m0 + rl;
            if (r >= M) continue;
            float S  = red[rl * 8 + 0] + red[rl * 8 + 1] + red[rl * 8 + 2] + red[rl * 8 + 3];
            float S2 = red[rl * 8 + 4] + red[rl * 8 + 5] + red[rl * 8 + 6] + red[rl * 8 + 7];
            float mean = S * (1.0f / HIDC);
            float var = S2 * (1.0f / HIDC) - mean * mean;
            float rstd = rsqrtf(var + 1e-5f);
#pragma unroll
            for (int j = 0; j < 8; j++) {
                int c = warp_n * 64 + j * 8 + 2 * t;
                float2 gv = *(const float2*)&lng[c];
                float2 bv = *(const float2*)&lnb[c];
                float vx = (acc[i][j][half_ * 2 + 0] - mean) * rstd * gv.x + bv.x;
                float vy = (acc[i][j][half_ * 2 + 1] - mean) * rstd * gv.y + bv.y;
                *(float2*)&outF[(size_t)r * HIDC + c] = make_float2(vx, vy);
                if (OUT2)
                    *(__half2*)&outH[(size_t)r * HIDC + c] =
                        __float22half2_rn(make_float2(vx, vy));
            }
        }
    }
}

// ---------------- weight pack ----------------
__global__ void pack_kernel(const float* Wq, const float* Wk, const float* Wv,
                            const float* Wew, const float* Web, const float* Weo,
                            const float* Wo_h, const float* Wo_e,
                            const float* W1, const float* W2, float* S) {
    int i = blockIdx.x * 256 + threadIdx.x;
    if (i < 196608) {
        int n = i >> 8, k = i & 255;
        float v = (n < 256) ? Wq[k * 256 + n]
                : (n < 512) ? Wk[k * 256 + n - 256]
                            : Wv[k * 256 + n - 512];
        ((__half*)(S + O_WQKV))[i] = __float2half(v);
    }
    int i2 = i - 196608;
    if (i2 >= 0 && i2 < 131072) {
        int n = i2 >> 8, k = i2 & 255, c = n >> 1;
        float v = (n & 1) ? Web[k * 256 + c] : Wew[k * 256 + c];
        ((__half*)(S + O_WEWB))[i2] = __float2half(v);
    }
    int i3 = i - 327680;
    if (i3 >= 0 && i3 < 65536) {
        int n = i3 >> 8, k = i3 & 255;
        ((__half*)(S + O_WEO))[i3] = __float2half(Weo[k * 256 + n]);
    }
    int i4 = i - 393216;
    if (i4 >= 0 && i4 < 65536) {
        int n = i4 >> 8, k = i4 & 255;
        ((__half*)(S + O_WOH))[i4] = __float2half(Wo_h[k * 256 + n]);
    }
    int i5 = i - 458752;
    if (i5 >= 0 && i5 < 65536) {
        int n = i5 >> 8, k = i5 & 255;
        ((__half*)(S + O_WOE))[i5] = __float2half(Wo_e[k * 256 + n]);
    }
    int i6 = i - 524288;
    if (i6 >= 0 && i6 < 131072) {
        int n = i6 >> 8, k = i6 & 255;
        ((__half*)(S + O_W1))[i6] = __float2half(W1[k * 512 + n]);
    }
    int i7 = i - 655360;
    if (i7 >= 0 && i7 < 131072) {
        int n = i7 >> 9, k = i7 & 511;
        ((__half*)(S + O_W2))[i7] = __float2half(W2[k * 256 + n]);
    }
}

// ---------------- scatter: 32B/thread unnormalized vector RED ----------------
__global__ void scatter_kernel(const float* __restrict__ exv,
                               const __half* __restrict__ V, const __half* __restrict__ Oe,
                               float* __restrict__ agg, float* __restrict__ rowv,
                               const int* __restrict__ dst, const int* __restrict__ src, int E) {
    long t = (long)blockIdx.x * 256 + threadIdx.x;
    if (t >= (long)E * 32) return;
    int e = (int)(t >> 5), q2 = (int)(t & 31);   // q2: 8-element group (one head = 4 groups)
    int h = q2 >> 2;
    int dn = dst[e], sn = src[e];
    float sc = exv[(size_t)e * NHEAD + h];
    int4 vv = *(const int4*)(V + (size_t)sn * 256 + q2 * 8);
    int4 ov = *(const int4*)(Oe + (size_t)e * 256 + q2 * 8);
    __half2* vh = (__half2*)&vv;
    __half2* oh = (__half2*)&ov;
    float2 v0 = __half22float2(vh[0]), v1 = __half22float2(vh[1]);
    float2 v2 = __half22float2(vh[2]), v3 = __half22float2(vh[3]);
    float2 o0 = __half22float2(oh[0]), o1 = __half22float2(oh[1]);
    float2 o2 = __half22float2(oh[2]), o3 = __half22float2(oh[3]);
    float* ap = &agg[(size_t)dn * HIDC + q2 * 8];
    float* rp = &rowv[(size_t)dn * HIDC + q2 * 8];
    redv4(ap,     v0.x * sc, v0.y * sc, v1.x * sc, v1.y * sc);
    redv4(ap + 4, v2.x * sc, v2.y * sc, v3.x * sc, v3.y * sc);
    redv4(rp,     o0.x * sc, o0.y * sc, o1.x * sc, o1.y * sc);
    redv4(rp + 4, o2.x * sc, o2.y * sc, o3.x * sc, o3.y * sc);
}

// ---------------- combine: On = half((agg + einsum(rowv, BW)) / ssum) ----------------
__global__ void combine_kernel(const float* __restrict__ agg, const float* __restrict__ rowv,
                               const float* __restrict__ ssum,
                               const float* __restrict__ BW, __half* __restrict__ On, int Nn) {
    __shared__ float sBW[32 * 8 * 32];
    __shared__ float srv[HIDC];
    int tid = threadIdx.x;
    for (int i = tid; i < 32 * 8 * 32; i += 256) sBW[i] = BW[i];
    int h = tid >> 5, c = tid & 31;
    for (int r = 0; r < 16; r++) {
        int n = blockIdx.x * 16 + r;
        __syncthreads();
        if (n < Nn) srv[tid] = rowv[(size_t)n * HIDC + tid];
        __syncthreads();
        if (n < Nn) {
            float s = agg[(size_t)n * HIDC + tid];
#pragma unroll
            for (int d = 0; d < 32; d++)
                s += srv[h * 32 + d] * sBW[d * HIDC + h * 32 + c];
            float inv = 1.0f / (ssum[n * NHEAD + h] + 1e-16f);
            On[(size_t)n * HIDC + tid] = __float2half(s * inv);
        }
    }
}

// ---------------- launch ----------------
extern "C" void kernel_launch(void* const* d_in, const int* in_sizes, int n_in,
                              void* d_out, int out_size) {
    const float* x     = (const float*)d_in[0];
    const float* conn  = (const float*)d_in[1];
    const float* Wq    = (const float*)d_in[2];
    const float* Wk    = (const float*)d_in[3];
    const float* Wv    = (const float*)d_in[4];
    const float* Wew   = (const float*)d_in[5];
    const float* Web   = (const float*)d_in[6];
    const float* beb   = (const float*)d_in[7];
    const float* Weo   = (const float*)d_in[8];
    const float* beo   = (const float*)d_in[9];
    const float* Aw    = (const float*)d_in[10];
    const float* BW    = (const float*)d_in[11];
    const float* Wo_h  = (const float*)d_in[12];
    const float* bo_h  = (const float*)d_in[13];
    const float* Wo_e  = (const float*)d_in[14];
    const float* bo_e  = (const float*)d_in[15];
    const float* ln1hg = (const float*)d_in[16];
    const float* ln1hb = (const float*)d_in[17];
    const float* ln1eg = (const float*)d_in[18];
    const float* ln1eb = (const float*)d_in[19];
    const float* W1    = (const float*)d_in[20];
    const float* b1    = (const float*)d_in[21];
    const float* W2    = (const float*)d_in[22];
    const float* b2    = (const float*)d_in[23];
    const float* ln2hg = (const float*)d_in[24];
    const float* ln2hb = (const float*)d_in[25];
    const int*   ei    = (const int*)d_in[26];

    int Nn = in_sizes[0] / HIDC;
    int Ee = in_sizes[26] / 2;
    const int* dst = ei;
    const int* src = ei + Ee;

    float* S = nullptr;
    cudaGetSymbolAddress((void**)&S, g_scratch);

    __half* QK   = (__half*)(S + O_QK);
    __half* Vb   = (__half*)(S + O_V);
    __half* cA   = (__half*)(S + O_CA);
    __half* aqk  = (__half*)(S + O_AQK);
    __half* Oe   = (__half*)(S + O_OE);
    float*  scb  = S + O_SCB;
    float*  ssum = S + O_SSUM;
    float*  agg  = S + O_AGG;
    float*  rowv = S + O_ROWV;
    __half* On   = (__half*)(S + O_ON);
    float*  hln  = S + O_HLN;
    __half* hlnt = (__half*)(S + O_HLNT);
    __half* ffn  = (__half*)(S + O_FFN);
    __half* wqkv = (__half*)(S + O_WQKV);
    __half* wewb = (__half*)(S + O_WEWB);
    __half* weo  = (__half*)(S + O_WEO);
    __half* woh  = (__half*)(S + O_WOH);
    __half* woe  = (__half*)(S + O_WOE);
    __half* w1   = (__half*)(S + O_W1);
    __half* w2   = (__half*)(S + O_W2);

    float* outH = (float*)d_out;
    float* outE = outH + (size_t)Nn * HIDC;

    cudaFuncSetAttribute(gemm_nt<0, 1, 0, 1, 4>, cudaFuncAttributeMaxDynamicSharedMemorySize, GNT_SMEM);
    cudaFuncSetAttribute(gemm_nt<0, 1, 0, 1, 2>, cudaFuncAttributeMaxDynamicSharedMemorySize, GNT_SMEM);
    cudaFuncSetAttribute(gemm_nt<2, 0, 0, 1, 4>, cudaFuncAttributeMaxDynamicSharedMemorySize, GNT_SMEM);
    cudaFuncSetAttribute(gemm_nt<0, 1, 1, 0, 2>, cudaFuncAttributeMaxDynamicSharedMemorySize, GNT_SMEM);
    cudaFuncSetAttribute(gemm_nt<1, 1, 0, 0, 4>, cudaFuncAttributeMaxDynamicSharedMemorySize, GNT_SMEM);
    cudaFuncSetAttribute(gemm_ln<1, 256>, cudaFuncAttributeMaxDynamicSharedMemorySize, GLN_SMEM);
    cudaFuncSetAttribute(gemm_ln<0, 256>, cudaFuncAttributeMaxDynamicSharedMemorySize, GLN_SMEM);
    cudaFuncSetAttribute(gemm_ln<0, 512>, cudaFuncAttributeMaxDynamicSharedMemorySize, GLN_SMEM);

    // side stream + events (created once; fallback to serial)
    static cudaStream_t s1 = nullptr;
    static cudaEvent_t evRoot = nullptr, evQK = nullptr, evV = nullptr,
                       evFork = nullptr, evJoin = nullptr, evMS = nullptr;
    static bool streams_ok = false;
    static bool tried = false;
    if (!tried) {
        tried = true;
        streams_ok =
            (cudaStreamCreateWithFlags(&s1, cudaStreamNonBlocking) == cudaSuccess) &&
            (cudaEventCreateWithFlags(&evRoot, cudaEventDisableTiming) == cudaSuccess) &&
            (cudaEventCreateWithFlags(&evQK, cudaEventDisableTiming) == cudaSuccess) &&
            (cudaEventCreateWithFlags(&evV, cudaEventDisableTiming) == cudaSuccess) &&
            (cudaEventCreateWithFlags(&evFork, cudaEventDisableTiming) == cudaSuccess) &&
            (cudaEventCreateWithFlags(&evJoin, cudaEventDisableTiming) == cudaSuccess) &&
            (cudaEventCreateWithFlags(&evMS, cudaEventDisableTiming) == cudaSuccess);
    }

    const size_t msBytes = ((size_t)NMAXC * 8 + (size_t)Nn * 512) * sizeof(float);

    if (streams_ok) {
        // fork s1 from the capturing stream FIRST, then issue memset on s1
        cudaEventRecord(evRoot, 0);
        cudaStreamWaitEvent(s1, evRoot, 0);
        cudaMemsetAsync(ssum, 0, msBytes, s1);
        cudaEventRecord(evMS, s1);
    } else {
        cudaMemsetAsync(ssum, 0, msBytes);
    }
    // pack weights (stream 0, overlaps memset)
    pack_kernel<<<cdiv(786432, 256), 256>>>(Wq, Wk, Wv, Wew, Web, Weo, Wo_h, Wo_e, W1, W2, S);

    int gmN = cdiv(Nn, 128);
    int gmE = cdiv(Ee, 128);

    // QK = x @ Wqk  [N, 512] (half out)
    gemm_nt<0, 1, 0, 1, 4><<<gmN, 256, GNT_SMEM>>>(
        x, wqkv, nullptr, QK, Nn,
        nullptr, nullptr, nullptr, nullptr, nullptr, nullptr);

    if (streams_ok) {
        cudaEventRecord(evQK, 0);
        cudaStreamWaitEvent(s1, evQK, 0);
        // V = x @ Wv  [N, 256] on side stream (overlaps aqk + EwEb)
        gemm_nt<0, 1, 0, 1, 2><<<gmN, 256, GNT_SMEM, s1>>>(
            x, wqkv + (size_t)512 * 256, nullptr, Vb, Nn,
            nullptr, nullptr, nullptr, nullptr, nullptr, nullptr);
        cudaEventRecord(evV, s1);
    } else {
        gemm_nt<0, 1, 0, 1, 2><<<gmN, 256, GNT_SMEM>>>(
            x, wqkv + (size_t)512 * 256, nullptr, Vb, Nn,
            nullptr, nullptr, nullptr, nullptr, nullptr, nullptr);
    }

    // aqk[e] = Q[dst[e]] + K[src[e]]  (2 edges per warp)
    aqk_kernel<<<cdiv(Ee, 16), 256>>>(QK, aqk, dst, src, Ee);
    // fused EwEb GEMM + edge message: conn(fp32) -> cA (half)
    gemm_nt<2, 0, 0, 1, 4><<<gmE, 256, GNT_SMEM>>>(
        conn, wewb, beb, cA, Ee,
        dst, src, aqk, nullptr, nullptr, nullptr);
    // ssum/agg/rowv must be zeroed before score atomics
    if (streams_ok) cudaStreamWaitEvent((cudaStream_t)0, evMS, 0);
    // Oe = cA @ WeoT + beo (half) + fused score/clamp/exp/segment-sum
    gemm_nt<0, 1, 1, 0, 2><<<gmE, 256, GNT_SMEM>>>(
        cA, weo, beo, Oe, Ee,
        dst, nullptr, nullptr, Aw, scb, ssum);

    // ---- fork: e-path output GEMM+LN concurrent with attention chain ----
    if (streams_ok) {
        cudaEventRecord(evFork, 0);
        cudaStreamWaitEvent(s1, evFork, 0);
        gemm_ln<0, 256><<<cdiv(Ee, 64), 256, GLN_SMEM, s1>>>(
            Oe, woe, bo_e, conn, ln1eg, ln1eb, outE, nullptr, Ee);
        cudaEventRecord(evJoin, s1);
        cudaStreamWaitEvent((cudaStream_t)0, evV, 0);  // V ready before scatter
    }

    // attention chain (default stream)
    scatter_kernel<<<(int)cdiv((long)Ee * 32, 256), 256>>>(scb, Vb, Oe, agg, rowv, dst, src, Ee);
    combine_kernel<<<cdiv(Nn, 16), 256>>>(agg, rowv, ssum, BW, On, Nn);

    if (!streams_ok) {
        gemm_ln<0, 256><<<cdiv(Ee, 64), 256, GLN_SMEM>>>(
            Oe, woe, bo_e, conn, ln1eg, ln1eb, outE, nullptr, Ee);
    }

    // h path: hln = LN1h(x + On @ Wo_h + bo_h), + half copy hlnt
    gemm_ln<1, 256><<<cdiv(Nn, 64), 256, GLN_SMEM>>>(
        On, woh, bo_h, x, ln1hg, ln1hb, hln, hlnt, Nn);

    // FFN: ffn = relu(hlnt @ W1 + b1) (half)
    gemm_nt<1, 1, 0, 0, 4><<<gmN, 256, GNT_SMEM>>>(
        hlnt, w1, b1, ffn, Nn,
        nullptr, nullptr, nullptr, nullptr, nullptr, nullptr);
    // outH = LN2h(hln + ffn @ W2 + b2)  (K=512, fused)
    gemm_ln<0, 512><<<cdiv(Nn, 64), 256, GLN_SMEM>>>(
        ffn, w2, b2, hln, ln2hg, ln2hb, outH, nullptr, Nn);

    // ---- join ----
    if (streams_ok) {
        cudaStreamWaitEvent((cudaStream_t)0, evJoin, 0);
    }
}